// round 3
// baseline (speedup 1.0000x reference)
#include <cuda_runtime.h>
#include <math.h>

#ifndef M_PI
#define M_PI 3.14159265358979323846
#endif

#define NBETA   12
#define NALPHA  12
#define NGRID   (NBETA * NALPHA)   // 144
#define DIM     36
#define NCH     128
#define NTYPE   10
#define WSIZE   (3 * NTYPE * NCH * 6)   // 23040

// ---- hard-coded 12-point Gauss-Legendre nodes/weights ----
__constant__ double c_glx[NBETA] = {
    -0.9815606342467192, -0.9041172563704749, -0.7699026741943047,
    -0.5873179542866175, -0.3678314989981802, -0.1252334085114689,
     0.1252334085114689,  0.3678314989981802,  0.5873179542866175,
     0.7699026741943047,  0.9041172563704749,  0.9815606342467192
};
__constant__ double c_glw[NBETA] = {
    0.0471753363865118, 0.1069393259953184, 0.1600783285433462,
    0.2031674267230659, 0.2334925365383548, 0.2491470458134028,
    0.2491470458134028, 0.2334925365383548, 0.2031674267230659,
    0.1600783285433462, 0.1069393259953184, 0.0471753363865118
};

// Full dense tables, literal transcription of the reference build_s2grid.
__device__ float g_Y [NGRID * DIM];   // Y[(b*12+a)*36 + k]
__device__ float g_Yw[NGRID * DIM];

__global__ void init_tables_kernel() {
    int b = threadIdx.x;
    if (b >= NBETA) return;

    double x = c_glx[b];
    double w = c_glw[b];

    // normalized associated Legendre Pbar_l^m(x), no CS phase
    double P[6][6];
    double s = sqrt(fmax(1.0 - x * x, 0.0));
    P[0][0] = sqrt(1.0 / (4.0 * M_PI));
    for (int m = 1; m <= 5; ++m)
        P[m][m] = sqrt((2.0 * m + 1.0) / (2.0 * m)) * s * P[m - 1][m - 1];
    for (int m = 0; m < 5; ++m)
        P[m + 1][m] = sqrt(2.0 * m + 3.0) * x * P[m][m];
    for (int m = 0; m <= 5; ++m)
        for (int l = m + 2; l <= 5; ++l) {
            double aa = sqrt((4.0 * l * l - 1.0) / ((double)l * l - (double)m * m));
            double bb = sqrt((((l - 1.0) * (l - 1.0)) - (double)m * m) /
                             (4.0 * (l - 1.0) * (l - 1.0) - 1.0));
            P[l][m] = aa * (x * P[l - 1][m] - bb * P[l - 2][m]);
        }

    double wfac = w * (2.0 * M_PI / (double)NALPHA);
    double s2 = sqrt(2.0);

    for (int a = 0; a < NALPHA; ++a) {
        double alpha = a * (2.0 * M_PI / (double)NALPHA);
        for (int l = 0; l <= 5; ++l) {
            for (int m = -l; m <= l; ++m) {
                int idx = l * l + l + m;
                double plm = P[l][m < 0 ? -m : m];
                double ang;
                if (m > 0)       ang = s2 * cos((double)m * alpha);
                else if (m == 0) ang = 1.0;
                else             ang = s2 * sin((double)(-m) * alpha);
                double y = plm * ang;
                g_Y [(b * NALPHA + a) * DIM + idx] = (float)y;
                g_Yw[(b * NALPHA + a) * DIM + idx] = (float)(y * wfac);
            }
        }
    }
}

// ---------------------------------------------------------------------------
// Dense main kernel: one block per atom, one thread per channel.
// Literal transcription of the reference einsums.
// ---------------------------------------------------------------------------
__global__ __launch_bounds__(NCH) void tp_main_kernel(
    const float* __restrict__ feat,    // [n, 128, 36]
    const float* __restrict__ atype,   // [n, 10]
    const float* __restrict__ W,       // [3, 10, 128, 6]
    float* __restrict__ out)           // [n, 128, 36]
{
    constexpr int KL[DIM] = {0,
                             1,1,1,
                             2,2,2,2,2,
                             3,3,3,3,3,3,3,
                             4,4,4,4,4,4,4,4,4,
                             5,5,5,5,5,5,5,5,5,5,5};

    __shared__ float sY [NGRID * DIM];
    __shared__ float sYw[NGRID * DIM];
    __shared__ float sAt[16];

    const int tid = threadIdx.x;
    const int n   = blockIdx.x;

    for (int i = tid; i < NGRID * DIM; i += NCH) { sY[i] = g_Y[i]; sYw[i] = g_Yw[i]; }
    if (tid < NTYPE) sAt[tid] = atype[(size_t)n * NTYPE + tid];
    __syncthreads();

    const size_t base = ((size_t)n * NCH + tid) * DIM;

    // ---- load coefficients ----
    float c0[DIM];
    {
        const float4* fp = reinterpret_cast<const float4*>(feat + base);
        #pragma unroll
        for (int q = 0; q < 9; ++q) {
            float4 v = fp[q];
            c0[4*q+0] = v.x; c0[4*q+1] = v.y; c0[4*q+2] = v.z; c0[4*q+3] = v.w;
        }
    }

    // ---- atom-type-weighted per-l weights, all 3 correlation orders ----
    float w0[6], w1[6], w2[6];
    #pragma unroll
    for (int l = 0; l < 6; ++l) { w0[l] = 0.f; w1[l] = 0.f; w2[l] = 0.f; }
    #pragma unroll 1
    for (int e = 0; e < NTYPE; ++e) {
        float a = sAt[e];
        const float* Wp = W + ((size_t)e * NCH + tid) * 6;
        #pragma unroll
        for (int l = 0; l < 6; ++l) {
            w0[l] = fmaf(a, Wp[l],                     w0[l]);
            w1[l] = fmaf(a, Wp[NTYPE * NCH * 6 + l],   w1[l]);
            w2[l] = fmaf(a, Wp[2 * NTYPE * NCH * 6 + l], w2[l]);
        }
    }

    // ========== pass A: p1 = Yw^T ( (Y c0) * (Y c0) ) ==========
    float p1[DIM];
    #pragma unroll
    for (int k = 0; k < DIM; ++k) p1[k] = 0.f;

    #pragma unroll 1
    for (int ba = 0; ba < NGRID; ++ba) {
        const float* yr  = sY  + ba * DIM;
        const float* ywr = sYw + ba * DIM;
        float f = 0.f;
        #pragma unroll
        for (int q = 0; q < 9; ++q) {
            float4 yv = *reinterpret_cast<const float4*>(yr + 4 * q);
            f = fmaf(yv.x, c0[4*q+0], f);
            f = fmaf(yv.y, c0[4*q+1], f);
            f = fmaf(yv.z, c0[4*q+2], f);
            f = fmaf(yv.w, c0[4*q+3], f);
        }
        float g = f * f;
        #pragma unroll
        for (int q = 0; q < 9; ++q) {
            float4 wv = *reinterpret_cast<const float4*>(ywr + 4 * q);
            p1[4*q+0] = fmaf(g, wv.x, p1[4*q+0]);
            p1[4*q+1] = fmaf(g, wv.y, p1[4*q+1]);
            p1[4*q+2] = fmaf(g, wv.z, p1[4*q+2]);
            p1[4*q+3] = fmaf(g, wv.w, p1[4*q+3]);
        }
    }

    // ========== pass B: p2 = Yw^T ( (Y p1) * (Y c0) ) ==========
    float p2[DIM];
    #pragma unroll
    for (int k = 0; k < DIM; ++k) p2[k] = 0.f;

    #pragma unroll 1
    for (int ba = 0; ba < NGRID; ++ba) {
        const float* yr  = sY  + ba * DIM;
        const float* ywr = sYw + ba * DIM;
        float f0 = 0.f, f1 = 0.f;
        #pragma unroll
        for (int q = 0; q < 9; ++q) {
            float4 yv = *reinterpret_cast<const float4*>(yr + 4 * q);
            f0 = fmaf(yv.x, c0[4*q+0], f0);
            f0 = fmaf(yv.y, c0[4*q+1], f0);
            f0 = fmaf(yv.z, c0[4*q+2], f0);
            f0 = fmaf(yv.w, c0[4*q+3], f0);
            f1 = fmaf(yv.x, p1[4*q+0], f1);
            f1 = fmaf(yv.y, p1[4*q+1], f1);
            f1 = fmaf(yv.z, p1[4*q+2], f1);
            f1 = fmaf(yv.w, p1[4*q+3], f1);
        }
        float g = f0 * f1;
        #pragma unroll
        for (int q = 0; q < 9; ++q) {
            float4 wv = *reinterpret_cast<const float4*>(ywr + 4 * q);
            p2[4*q+0] = fmaf(g, wv.x, p2[4*q+0]);
            p2[4*q+1] = fmaf(g, wv.y, p2[4*q+1]);
            p2[4*q+2] = fmaf(g, wv.z, p2[4*q+2]);
            p2[4*q+3] = fmaf(g, wv.w, p2[4*q+3]);
        }
    }

    // ---- final combine + vectorized store ----
    float* op = out + base;
    #pragma unroll
    for (int q = 0; q < 9; ++q) {
        float4 v;
        #pragma unroll
        for (int j = 0; j < 4; ++j) {
            int k = 4 * q + j;
            float r = w0[KL[k]] * c0[k];
            r = fmaf(w1[KL[k]], p1[k], r);
            r = fmaf(w2[KL[k]], p2[k], r);
            (&v.x)[j] = r;
        }
        *reinterpret_cast<float4*>(op + 4 * q) = v;
    }
}

// ---------------------------------------------------------------------------
extern "C" void kernel_launch(void* const* d_in, const int* in_sizes, int n_in,
                              void* d_out, int out_size) {
    // Bind inputs BY SIZE, not by position, to eliminate ordering assumptions:
    //   weights: exactly 3*10*128*6 = 23040 elements
    //   feat:    n*128*36  (largest)
    //   atype:   n*10
    const float* feat  = nullptr;
    const float* atype = nullptr;
    const float* W     = nullptr;

    // feat = largest input
    int fi = 0;
    for (int i = 1; i < n_in; ++i) if (in_sizes[i] > in_sizes[fi]) fi = i;
    feat = (const float*)d_in[fi];
    int n_atoms = in_sizes[fi] / (NCH * DIM);

    for (int i = 0; i < n_in; ++i) {
        if (i == fi) continue;
        if (in_sizes[i] == WSIZE && W == nullptr && in_sizes[i] != n_atoms * NTYPE) {
            W = (const float*)d_in[i];
        } else if (in_sizes[i] == n_atoms * NTYPE && atype == nullptr) {
            atype = (const float*)d_in[i];
        } else if (W == nullptr) {
            W = (const float*)d_in[i];
        } else {
            atype = (const float*)d_in[i];
        }
    }
    // Fallback to positional if anything unresolved
    if (!atype) atype = (const float*)d_in[1];
    if (!W)     W     = (const float*)d_in[2];

    float* out = (float*)d_out;

    init_tables_kernel<<<1, 32>>>();
    tp_main_kernel<<<n_atoms, NCH>>>(feat, atype, W, out);
}

// round 5
// speedup vs baseline: 4.1716x; 4.1716x over previous
#include <cuda_runtime.h>
#include <math.h>

#ifndef M_PI
#define M_PI 3.14159265358979323846
#endif

#define NBETA   12
#define NALPHA  12
#define DIM     36
#define NCH     128
#define NTYPE   10
#define WSIZE   (3 * NTYPE * NCH * 6)   // 23040

// ---- hard-coded 12-point Gauss-Legendre nodes/weights ----
__constant__ double c_glx[NBETA] = {
    -0.9815606342467192, -0.9041172563704749, -0.7699026741943047,
    -0.5873179542866175, -0.3678314989981802, -0.1252334085114689,
     0.1252334085114689,  0.3678314989981802,  0.5873179542866175,
     0.7699026741943047,  0.9041172563704749,  0.9815606342467192
};
__constant__ double c_glw[NBETA] = {
    0.0471753363865118, 0.1069393259953184, 0.1600783285433462,
    0.2031674267230659, 0.2334925365383548, 0.2491470458134028,
    0.2491470458134028, 0.2334925365383548, 0.2031674267230659,
    0.1600783285433462, 0.1069393259953184, 0.0471753363865118
};

// Factored tables packed in ONE array so the main kernel loads them with a
// single strided loop (the round-1/2/4 bug was a `tid < 144` guard with a
// 128-thread block leaving sAng[128..143] as garbage).
//   [0,432)    Pk
//   [432,864)  Pwk
//   [864,1008) ang  (a*12 + mi, mi = m+5, [11] pad = 0)
#define TBL_PK   0
#define TBL_PW   432
#define TBL_ANG  864
#define TBL_SIZE 1008
__device__ float g_tbl[TBL_SIZE];

__global__ void init_tables_kernel() {
    int t = threadIdx.x;
    if (t < NBETA) {
        double x = c_glx[t];
        double w = c_glw[t];

        // normalized associated Legendre Pbar_l^m(x), no CS phase
        double P[6][6];
        double s = sqrt(fmax(1.0 - x * x, 0.0));
        P[0][0] = sqrt(1.0 / (4.0 * M_PI));
        for (int m = 1; m <= 5; ++m)
            P[m][m] = sqrt((2.0 * m + 1.0) / (2.0 * m)) * s * P[m - 1][m - 1];
        for (int m = 0; m < 5; ++m)
            P[m + 1][m] = sqrt(2.0 * m + 3.0) * x * P[m][m];
        for (int m = 0; m <= 5; ++m)
            for (int l = m + 2; l <= 5; ++l) {
                double aa = sqrt((4.0 * l * l - 1.0) / ((double)l * l - (double)m * m));
                double bb = sqrt((((l - 1.0) * (l - 1.0)) - (double)m * m) /
                                 (4.0 * (l - 1.0) * (l - 1.0) - 1.0));
                P[l][m] = aa * (x * P[l - 1][m] - bb * P[l - 2][m]);
            }

        double wfac = w * (2.0 * M_PI / (double)NALPHA);
        for (int k = 0; k < DIM; ++k) {
            int l = 0;
            while (k >= (l + 1) * (l + 1)) ++l;
            int m = k - l * l - l;
            double v = P[l][m < 0 ? -m : m];
            g_tbl[TBL_PK + t * DIM + k] = (float)v;
            g_tbl[TBL_PW + t * DIM + k] = (float)(v * wfac);
        }
    } else if (t < NBETA + NALPHA) {
        int a = t - NBETA;
        double alpha = a * (2.0 * M_PI / (double)NALPHA);
        double s2 = sqrt(2.0);
        for (int mi = 0; mi < 12; ++mi) g_tbl[TBL_ANG + a * 12 + mi] = 0.0f;
        g_tbl[TBL_ANG + a * 12 + 5] = 1.0f;                                   // m = 0
        for (int m = 1; m <= 5; ++m) {
            g_tbl[TBL_ANG + a * 12 + 5 + m] = (float)(s2 * cos(m * alpha));   // m > 0
            g_tbl[TBL_ANG + a * 12 + 5 - m] = (float)(s2 * sin(m * alpha));   // m < 0
        }
    }
}

// ---------------------------------------------------------------------------
// Factored main kernel: one block per atom, one thread per channel.
// to_grid/from_grid separated through the m-index; fg cached in smem.
// ---------------------------------------------------------------------------
__global__ __launch_bounds__(NCH) void tp_main_kernel(
    const float* __restrict__ feat,    // [n, 128, 36]
    const float* __restrict__ atype,   // [n, 10]
    const float* __restrict__ W,       // [3, 10, 128, 6]
    float* __restrict__ out)           // [n, 128, 36]
{
    constexpr int KM[DIM] = {5,
                             4,5,6,
                             3,4,5,6,7,
                             2,3,4,5,6,7,8,
                             1,2,3,4,5,6,7,8,9,
                             0,1,2,3,4,5,6,7,8,9,10};
    constexpr int KL[DIM] = {0,
                             1,1,1,
                             2,2,2,2,2,
                             3,3,3,3,3,3,3,
                             4,4,4,4,4,4,4,4,4,
                             5,5,5,5,5,5,5,5,5,5,5};

    extern __shared__ float sm[];
    float* sPk  = sm + TBL_PK;    // 432
    float* sPw  = sm + TBL_PW;    // 432
    float* sAng = sm + TBL_ANG;   // 144
    float* sAt  = sm + TBL_SIZE;  // 16 (pad to 1024)
    float* sFg  = sm + 1024;      // 144 * 128

    const int tid = threadIdx.x;
    const int n   = blockIdx.x;

    // strided table load — covers ALL 1008 entries with 128 threads
    #pragma unroll
    for (int i = tid; i < TBL_SIZE; i += NCH) sm[i] = g_tbl[i];
    if (tid < NTYPE) sAt[tid] = atype[(size_t)n * NTYPE + tid];
    __syncthreads();

    const size_t base = ((size_t)n * NCH + tid) * DIM;

    // ---- load coefficients ----
    float c0[DIM];
    {
        const float4* fp = reinterpret_cast<const float4*>(feat + base);
        #pragma unroll
        for (int q = 0; q < 9; ++q) {
            float4 v = fp[q];
            c0[4*q+0] = v.x; c0[4*q+1] = v.y; c0[4*q+2] = v.z; c0[4*q+3] = v.w;
        }
    }

    // ---- atom-type-weighted per-l weights, all 3 correlation orders ----
    float w0[6], w1[6], w2[6];
    #pragma unroll
    for (int l = 0; l < 6; ++l) { w0[l] = 0.f; w1[l] = 0.f; w2[l] = 0.f; }
    #pragma unroll 1
    for (int e = 0; e < NTYPE; ++e) {
        float a = sAt[e];
        const float* Wp = W + ((size_t)e * NCH + tid) * 6;
        #pragma unroll
        for (int l = 0; l < 6; ++l) {
            w0[l] = fmaf(a, Wp[l],                       w0[l]);
            w1[l] = fmaf(a, Wp[NTYPE * NCH * 6 + l],     w1[l]);
            w2[l] = fmaf(a, Wp[2 * NTYPE * NCH * 6 + l], w2[l]);
        }
    }

    // =================== pass A: fg = Y c0 ; p1 = Yw^T (fg*fg) ===============
    float p1[DIM];
    #pragma unroll
    for (int k = 0; k < DIM; ++k) p1[k] = 0.f;

    #pragma unroll 1
    for (int b = 0; b < NBETA; ++b) {
        float t[11];
        #pragma unroll
        for (int mi = 0; mi < 11; ++mi) t[mi] = 0.f;
        #pragma unroll
        for (int k = 0; k < DIM; ++k)
            t[KM[k]] = fmaf(sPk[b * DIM + k], c0[k], t[KM[k]]);

        float u[11];
        #pragma unroll
        for (int mi = 0; mi < 11; ++mi) u[mi] = 0.f;
        #pragma unroll
        for (int a = 0; a < NALPHA; ++a) {
            const float* an = sAng + a * 12;
            float f = t[0] * an[0];
            #pragma unroll
            for (int mi = 1; mi < 11; ++mi) f = fmaf(t[mi], an[mi], f);
            sFg[(b * NALPHA + a) * NCH + tid] = f;
            float g = f * f;
            #pragma unroll
            for (int mi = 0; mi < 11; ++mi) u[mi] = fmaf(g, an[mi], u[mi]);
        }
        #pragma unroll
        for (int k = 0; k < DIM; ++k)
            p1[k] = fmaf(sPw[b * DIM + k], u[KM[k]], p1[k]);
    }

    // fold nu=0 and nu=1 contributions
    float acc[DIM];
    #pragma unroll
    for (int k = 0; k < DIM; ++k)
        acc[k] = w0[KL[k]] * c0[k] + w1[KL[k]] * p1[k];

    // ============ pass B: p2 = Yw^T ((Y p1) * fg) ============================
    float p2[DIM];
    #pragma unroll
    for (int k = 0; k < DIM; ++k) p2[k] = 0.f;

    #pragma unroll 1
    for (int b = 0; b < NBETA; ++b) {
        float t[11];
        #pragma unroll
        for (int mi = 0; mi < 11; ++mi) t[mi] = 0.f;
        #pragma unroll
        for (int k = 0; k < DIM; ++k)
            t[KM[k]] = fmaf(sPk[b * DIM + k], p1[k], t[KM[k]]);

        float u[11];
        #pragma unroll
        for (int mi = 0; mi < 11; ++mi) u[mi] = 0.f;
        #pragma unroll
        for (int a = 0; a < NALPHA; ++a) {
            const float* an = sAng + a * 12;
            float f = t[0] * an[0];
            #pragma unroll
            for (int mi = 1; mi < 11; ++mi) f = fmaf(t[mi], an[mi], f);
            float g = f * sFg[(b * NALPHA + a) * NCH + tid];
            #pragma unroll
            for (int mi = 0; mi < 11; ++mi) u[mi] = fmaf(g, an[mi], u[mi]);
        }
        #pragma unroll
        for (int k = 0; k < DIM; ++k)
            p2[k] = fmaf(sPw[b * DIM + k], u[KM[k]], p2[k]);
    }

    // ---- final combine + vectorized store ----
    float* op = out + base;
    #pragma unroll
    for (int q = 0; q < 9; ++q) {
        float4 v;
        v.x = fmaf(w2[KL[4*q+0]], p2[4*q+0], acc[4*q+0]);
        v.y = fmaf(w2[KL[4*q+1]], p2[4*q+1], acc[4*q+1]);
        v.z = fmaf(w2[KL[4*q+2]], p2[4*q+2], acc[4*q+2]);
        v.w = fmaf(w2[KL[4*q+3]], p2[4*q+3], acc[4*q+3]);
        *reinterpret_cast<float4*>(op + 4 * q) = v;
    }
}

// ---------------------------------------------------------------------------
extern "C" void kernel_launch(void* const* d_in, const int* in_sizes, int n_in,
                              void* d_out, int out_size) {
    // Bind inputs BY SIZE:
    //   feat  = largest input, n*128*36
    //   W     = exactly 23040 elements
    //   atype = n*10
    const float* feat  = nullptr;
    const float* atype = nullptr;
    const float* W     = nullptr;

    int fi = 0;
    for (int i = 1; i < n_in; ++i) if (in_sizes[i] > in_sizes[fi]) fi = i;
    feat = (const float*)d_in[fi];
    int n_atoms = in_sizes[fi] / (NCH * DIM);

    for (int i = 0; i < n_in; ++i) {
        if (i == fi) continue;
        if (in_sizes[i] == WSIZE && W == nullptr && in_sizes[i] != n_atoms * NTYPE) {
            W = (const float*)d_in[i];
        } else if (in_sizes[i] == n_atoms * NTYPE && atype == nullptr) {
            atype = (const float*)d_in[i];
        } else if (W == nullptr) {
            W = (const float*)d_in[i];
        } else {
            atype = (const float*)d_in[i];
        }
    }
    if (!atype) atype = (const float*)d_in[1];
    if (!W)     W     = (const float*)d_in[2];

    float* out = (float*)d_out;

    size_t smem = (size_t)(1024 + NBETA * NALPHA * NCH) * sizeof(float); // 77824 B
    cudaFuncSetAttribute(tp_main_kernel,
                         cudaFuncAttributeMaxDynamicSharedMemorySize, (int)smem);

    init_tables_kernel<<<1, 32>>>();
    tp_main_kernel<<<n_atoms, NCH, smem>>>(feat, atype, W, out);
}